// round 11
// baseline (speedup 1.0000x reference)
#include <cuda_runtime.h>

// Problem constants (AdaBIGGAN last adaptive stage)
#define BB 32
#define CC 96
#define HH 128
#define WW 128
#define INF 148               // hypernet input dim

#define HW  (HH * WW)         // 16384 floats per (b,c) plane
#define HW4 (HW / 4)          // 4096 float4 per plane

#define NGRP 4                       // row-groups per channel (== gridDim.x)
#define ROWS_PER_GRP (CC / NGRP)     // 24
#define NPROD (CC * NGRP)            // 384 producer blocks
#define GRID_X (HW4 / 1024)          // 4
#define TOTAL_BLOCKS (GRID_X * BB * CC)   // 12288

// Scratch + sync state (no cudaMalloc allowed)
__device__ float        g_part [NPROD * INF];   // partial column sums of Wg_w
__device__ float        g_bpart[NPROD];         // partial sums of Wg_b
__device__ unsigned int g_done     = 0;         // producers finished
__device__ unsigned int g_consumed = 0;         // blocks finished (reset logic)

// ---------------------------------------------------------------------------
// Single fused kernel.
// Producers = first NPROD blocks in linear placement order (guaranteed wave-1
// residents; they never spin before producing => no deadlock). They reduce one
// (c,g) 24x148 slice of Wg_w + the matching Wg_b slice, then release g_done.
// All blocks acquire-wait on g_done==NPROD, compute the per-(b,c) dot
// (scale = y.wsum + bsum, bias = y.Bg_w[c] + Bg_b[c]) and run the HBM stream
// out = relu(h*scale + bias). Last block resets counters (replay-safe).
// ---------------------------------------------------------------------------
__global__ __launch_bounds__(256) void fused_kernel(
    const float* __restrict__ h,
    const float* __restrict__ y,      // [B, IN]
    const float* __restrict__ Wg_w,   // [C*C, IN]
    const float* __restrict__ Wg_b,   // [C*C]
    const float* __restrict__ Bg_w,   // [C, IN]
    const float* __restrict__ Bg_b,   // [C]
    float* __restrict__ out)
{
    const int bc     = blockIdx.y;        // b*CC + c
    const int c      = bc % CC;
    const int b      = bc / CC;
    const int tid    = threadIdx.x;
    const int linear = blockIdx.x + GRID_X * blockIdx.y;

    // ---- issue the streaming loads FIRST (independent of everything) ----
    const float4* __restrict__ hp = reinterpret_cast<const float4*>(h  + (size_t)bc * HW);
    float4*       __restrict__ op = reinterpret_cast<float4*>      (out + (size_t)bc * HW);
    const int base = blockIdx.x * 1024 + tid;

    float4 v0 = __ldcs(hp + base);
    float4 v1 = __ldcs(hp + base + 256);
    float4 v2 = __ldcs(hp + base + 512);
    float4 v3 = __ldcs(hp + base + 768);

    // ---- producer phase: first NPROD linear blocks reduce Wg_w slices ----
    if (linear < NPROD) {
        const int pc = linear >> 2;       // channel   (== bc here, b==0)
        const int pg = linear & 3;        // row group (== blockIdx.x)
        const float* pbase = Wg_w + ((size_t)pc * CC + pg * ROWS_PER_GRP) * INF;

        if (tid < INF) {
            float s = 0.f;
            #pragma unroll
            for (int r = 0; r < ROWS_PER_GRP; ++r)
                s += __ldg(pbase + (size_t)r * INF + tid);
            g_part[linear * INF + tid] = s;
        }
        if (tid >= 192 && tid < 224) {    // one warp for the Wg_b partial
            const int l = tid - 192;
            float pb = (l < ROWS_PER_GRP)
                     ? __ldg(Wg_b + pc * CC + pg * ROWS_PER_GRP + l) : 0.f;
            #pragma unroll
            for (int o = 16; o > 0; o >>= 1)
                pb += __shfl_down_sync(0xffffffffu, pb, o);
            if (l == 0) g_bpart[linear] = pb;
        }
        __syncthreads();                  // all slice writes done in this block
        if (tid == 0) {
            __threadfence();              // release g_part/g_bpart
            atomicAdd(&g_done, 1u);
        }
    }

    // ---- acquire-wait for all producers ----
    if (tid == 0) {
        while (atomicAdd(&g_done, 0u) < (unsigned)NPROD)
            __nanosleep(64);
    }
    __syncthreads();
    __threadfence();                      // acquire: order g_part reads after flag

    // ---- prologue: per-(b,c) scale/bias dot (operands L2-resident) ----
    __shared__ float sh_ds[8], sh_db[8];
    __shared__ float sh_s, sh_b;

    float ds = 0.f, db = 0.f;
    if (tid < INF) {
        const float yv = __ldg(y + b * INF + tid);
        const float* pp = g_part + (size_t)(c * NGRP) * INF + tid;
        const float w = pp[0] + pp[INF] + pp[2 * INF] + pp[3 * INF];
        ds = yv * w;
        db = yv * __ldg(Bg_w + c * INF + tid);
    }
    #pragma unroll
    for (int o = 16; o > 0; o >>= 1) {
        ds += __shfl_down_sync(0xffffffffu, ds, o);
        db += __shfl_down_sync(0xffffffffu, db, o);
    }
    const int warp = tid >> 5, lane = tid & 31;
    if (lane == 0) { sh_ds[warp] = ds; sh_db[warp] = db; }
    __syncthreads();
    if (tid == 0) {
        float S = sh_ds[0] + sh_ds[1] + sh_ds[2] + sh_ds[3]
                + sh_ds[4] + sh_ds[5] + sh_ds[6] + sh_ds[7];
        float D = sh_db[0] + sh_db[1] + sh_db[2] + sh_db[3]
                + sh_db[4] + sh_db[5] + sh_db[6] + sh_db[7];
        const float* bp = g_bpart + c * NGRP;
        S += bp[0] + bp[1] + bp[2] + bp[3];
        D += __ldg(Bg_b + c);
        sh_s = S; sh_b = D;
    }
    __syncthreads();
    const float s  = sh_s;
    const float bi = sh_b;

    // ---- affine + relu + streaming stores ----
    v0.x = fmaxf(fmaf(v0.x, s, bi), 0.f);
    v0.y = fmaxf(fmaf(v0.y, s, bi), 0.f);
    v0.z = fmaxf(fmaf(v0.z, s, bi), 0.f);
    v0.w = fmaxf(fmaf(v0.w, s, bi), 0.f);
    v1.x = fmaxf(fmaf(v1.x, s, bi), 0.f);
    v1.y = fmaxf(fmaf(v1.y, s, bi), 0.f);
    v1.z = fmaxf(fmaf(v1.z, s, bi), 0.f);
    v1.w = fmaxf(fmaf(v1.w, s, bi), 0.f);
    v2.x = fmaxf(fmaf(v2.x, s, bi), 0.f);
    v2.y = fmaxf(fmaf(v2.y, s, bi), 0.f);
    v2.z = fmaxf(fmaf(v2.z, s, bi), 0.f);
    v2.w = fmaxf(fmaf(v2.w, s, bi), 0.f);
    v3.x = fmaxf(fmaf(v3.x, s, bi), 0.f);
    v3.y = fmaxf(fmaf(v3.y, s, bi), 0.f);
    v3.z = fmaxf(fmaf(v3.z, s, bi), 0.f);
    v3.w = fmaxf(fmaf(v3.w, s, bi), 0.f);

    __stcs(op + base,       v0);
    __stcs(op + base + 256, v1);
    __stcs(op + base + 512, v2);
    __stcs(op + base + 768, v3);

    // ---- replay-safe reset handshake ----
    __syncthreads();                      // every thread past its g_done read
    if (tid == 0) {
        const unsigned prev = atomicAdd(&g_consumed, 1u);
        if (prev == (unsigned)(TOTAL_BLOCKS - 1)) {
            atomicExch(&g_done, 0u);      // all blocks have consumed the flag
            atomicExch(&g_consumed, 0u);
        }
    }
}

// ---------------------------------------------------------------------------
// Launch. Input order per metadata: h, y, Wg_w, Wg_b, Bg_w, Bg_b
// ---------------------------------------------------------------------------
extern "C" void kernel_launch(void* const* d_in, const int* in_sizes, int n_in,
                              void* d_out, int out_size)
{
    const float* h    = (const float*)d_in[0];
    const float* y    = (const float*)d_in[1];
    const float* Wg_w = (const float*)d_in[2];
    const float* Wg_b = (const float*)d_in[3];
    const float* Bg_w = (const float*)d_in[4];
    const float* Bg_b = (const float*)d_in[5];
    float* out = (float*)d_out;

    dim3 grid(GRID_X, BB * CC);   // (4, 3072)
    fused_kernel<<<grid, 256>>>(h, y, Wg_w, Wg_b, Bg_w, Bg_b, out);
}

// round 12
// speedup vs baseline: 1.1355x; 1.1355x over previous
#include <cuda_runtime.h>

// Problem constants (AdaBIGGAN last adaptive stage)
#define BB 32
#define CC 96
#define HH 128
#define WW 128
#define INF 148               // hypernet input dim

#define HW  (HH * WW)         // 16384 floats per (b,c) plane
#define HW4 (HW / 4)          // 4096 float4 per plane

#define NGRP 4                // row-groups per channel in kernel 1
#define ROWS_PER_GRP (CC / NGRP)   // 24
#define GRID_X (HW4 / 1024)        // 4

// Scratch (no cudaMalloc allowed)
__device__ float g_part [CC * NGRP * INF];  // partial column sums of Wg_w
__device__ float g_bpart[CC * NGRP];        // partial sums of Wg_b

// ---------------------------------------------------------------------------
// Kernel 1 (primary): wide partial reduction of Wg_w / Wg_b.
// Block (c,g) sums rows j = g*24 .. g*24+23 of channel c's 96x148 slab,
// column-wise (coalesced in i). 384 blocks, 160 threads. ~1.5us.
// ---------------------------------------------------------------------------
__global__ __launch_bounds__(160) void part_kernel(
    const float* __restrict__ Wg_w,   // [C*C, IN]
    const float* __restrict__ Wg_b)   // [C*C]
{
    const int blk = blockIdx.x;          // 0..383
    const int c   = blk >> 2;
    const int g   = blk & 3;
    const int tid = threadIdx.x;

    const float* base = Wg_w + ((size_t)c * CC + g * ROWS_PER_GRP) * INF;

    if (tid < INF) {
        float s = 0.f;
        #pragma unroll
        for (int r = 0; r < ROWS_PER_GRP; ++r)
            s += __ldg(base + (size_t)r * INF + tid);
        g_part[blk * INF + tid] = s;
    }

    // Wg_b partial for this (c,g): 24 values, warp-0 shuffle reduce.
    if (tid < 32) {
        float pb = (tid < ROWS_PER_GRP)
                 ? __ldg(Wg_b + c * CC + g * ROWS_PER_GRP + tid) : 0.f;
        #pragma unroll
        for (int o = 16; o > 0; o >>= 1)
            pb += __shfl_down_sync(0xffffffffu, pb, o);
        if (tid == 0) g_bpart[blk] = pb;
    }
}

// ---------------------------------------------------------------------------
// Kernel 2 (secondary, PDL): fused dot-prologue + HBM stream.
// Launched with programmatic stream serialization: its blocks start while
// part_kernel still runs, issue their 4 front-batched h loads, THEN gate on
// cudaGridDependencySynchronize() before touching g_part/g_bpart.
//   out = relu(h * (y.wsum + bsum) + (y.Bg_w[c] + Bg_b[c]))
// ---------------------------------------------------------------------------
__global__ __launch_bounds__(256) void affine_relu_kernel(
    const float* __restrict__ h,
    const float* __restrict__ y,      // [B, IN]
    const float* __restrict__ Bg_w,   // [C, IN]
    const float* __restrict__ Bg_b,   // [C]
    float* __restrict__ out)
{
    const int bc  = blockIdx.y;           // b*CC + c (matches [B,C,H,W] planes)
    const int c   = bc % CC;
    const int b   = bc / CC;
    const int tid = threadIdx.x;

    // ---- issue the streaming loads FIRST (independent of the primary) ----
    const float4* __restrict__ hp = reinterpret_cast<const float4*>(h  + (size_t)bc * HW);
    float4*       __restrict__ op = reinterpret_cast<float4*>      (out + (size_t)bc * HW);
    const int base = blockIdx.x * 1024 + tid;

    float4 v0 = __ldcs(hp + base);
    float4 v1 = __ldcs(hp + base + 256);
    float4 v2 = __ldcs(hp + base + 512);
    float4 v3 = __ldcs(hp + base + 768);

    // ---- HW dependency gate: wait for part_kernel completion ----
    cudaGridDependencySynchronize();

    // ---- prologue: per-(b,c) scale/bias dot (operands L2-resident) ----
    __shared__ float sh_ds[8], sh_db[8];
    __shared__ float sh_s, sh_b;

    float ds = 0.f, db = 0.f;
    if (tid < INF) {
        const float yv = __ldg(y + b * INF + tid);
        const float* pp = g_part + (size_t)(c * NGRP) * INF + tid;
        const float w = pp[0] + pp[INF] + pp[2 * INF] + pp[3 * INF];
        ds = yv * w;
        db = yv * __ldg(Bg_w + c * INF + tid);
    }
    #pragma unroll
    for (int o = 16; o > 0; o >>= 1) {
        ds += __shfl_down_sync(0xffffffffu, ds, o);
        db += __shfl_down_sync(0xffffffffu, db, o);
    }
    const int warp = tid >> 5, lane = tid & 31;
    if (lane == 0) { sh_ds[warp] = ds; sh_db[warp] = db; }
    __syncthreads();
    if (tid == 0) {
        float S = sh_ds[0] + sh_ds[1] + sh_ds[2] + sh_ds[3]
                + sh_ds[4] + sh_ds[5] + sh_ds[6] + sh_ds[7];
        float D = sh_db[0] + sh_db[1] + sh_db[2] + sh_db[3]
                + sh_db[4] + sh_db[5] + sh_db[6] + sh_db[7];
        const float* bp = g_bpart + c * NGRP;
        S += bp[0] + bp[1] + bp[2] + bp[3];
        D += __ldg(Bg_b + c);
        sh_s = S; sh_b = D;
    }
    __syncthreads();
    const float s  = sh_s;
    const float bi = sh_b;

    // ---- affine + relu + streaming stores ----
    v0.x = fmaxf(fmaf(v0.x, s, bi), 0.f);
    v0.y = fmaxf(fmaf(v0.y, s, bi), 0.f);
    v0.z = fmaxf(fmaf(v0.z, s, bi), 0.f);
    v0.w = fmaxf(fmaf(v0.w, s, bi), 0.f);
    v1.x = fmaxf(fmaf(v1.x, s, bi), 0.f);
    v1.y = fmaxf(fmaf(v1.y, s, bi), 0.f);
    v1.z = fmaxf(fmaf(v1.z, s, bi), 0.f);
    v1.w = fmaxf(fmaf(v1.w, s, bi), 0.f);
    v2.x = fmaxf(fmaf(v2.x, s, bi), 0.f);
    v2.y = fmaxf(fmaf(v2.y, s, bi), 0.f);
    v2.z = fmaxf(fmaf(v2.z, s, bi), 0.f);
    v2.w = fmaxf(fmaf(v2.w, s, bi), 0.f);
    v3.x = fmaxf(fmaf(v3.x, s, bi), 0.f);
    v3.y = fmaxf(fmaf(v3.y, s, bi), 0.f);
    v3.z = fmaxf(fmaf(v3.z, s, bi), 0.f);
    v3.w = fmaxf(fmaf(v3.w, s, bi), 0.f);

    __stcs(op + base,       v0);
    __stcs(op + base + 256, v1);
    __stcs(op + base + 512, v2);
    __stcs(op + base + 768, v3);
}

// ---------------------------------------------------------------------------
// Launch. Input order per metadata: h, y, Wg_w, Wg_b, Bg_w, Bg_b
// Secondary kernel uses programmatic stream serialization (PDL) so its blocks
// launch while part_kernel is still running.
// ---------------------------------------------------------------------------
extern "C" void kernel_launch(void* const* d_in, const int* in_sizes, int n_in,
                              void* d_out, int out_size)
{
    const float* h    = (const float*)d_in[0];
    const float* y    = (const float*)d_in[1];
    const float* Wg_w = (const float*)d_in[2];
    const float* Wg_b = (const float*)d_in[3];
    const float* Bg_w = (const float*)d_in[4];
    const float* Bg_b = (const float*)d_in[5];
    float* out = (float*)d_out;

    part_kernel<<<CC * NGRP, 160>>>(Wg_w, Wg_b);

    cudaLaunchConfig_t cfg = {};
    cfg.gridDim  = dim3(GRID_X, BB * CC);   // (4, 3072)
    cfg.blockDim = dim3(256);
    cfg.dynamicSmemBytes = 0;
    cfg.stream = 0;

    cudaLaunchAttribute attr[1];
    attr[0].id = cudaLaunchAttributeProgrammaticStreamSerialization;
    attr[0].val.programmaticStreamSerializationAllowed = 1;
    cfg.attrs = attr;
    cfg.numAttrs = 1;

    cudaLaunchKernelEx(&cfg, affine_relu_kernel, h, y, Bg_w, Bg_b, out);
}